// round 1
// baseline (speedup 1.0000x reference)
#include <cuda_runtime.h>
#include <cuda_bf16.h>

#define NN 1024
#define MM 1024
#define EPSF 1e-4f
#define MAXB 64

// Scratch: per-batch row/col scale factors (no allocations allowed).
__device__ float g_r[MAXB * NN];
__device__ float g_c[MAXB * MM];

// -------------------------------------------------------------------------
// Iteration 0: column normalization. Sums ALL rows (mask applied after the
// divide in the reference), but only columns j < ncols ever matter.
// c_j = 1 / (sum_i s[i,j] + N*eps)   for j < ncols, else 0.
// -------------------------------------------------------------------------
__global__ void colsum0_kernel(const float* __restrict__ s,
                               const int* __restrict__ ncols) {
    int b = blockIdx.y;
    int j = blockIdx.x * blockDim.x + threadIdx.x;
    int nc = ncols[b];
    if (j >= nc) { g_c[b * MM + j] = 0.0f; return; }
    const float* sp = s + (size_t)b * NN * MM + j;
    float acc = 0.0f;
#pragma unroll 8
    for (int i = 0; i < NN; i++) acc += sp[(size_t)i * MM];
    acc += (float)NN * EPSF;
    g_c[b * MM + j] = 1.0f / acc;
}

// -------------------------------------------------------------------------
// Row step: r_i = 1 / sum_{j<ncols} (s[i,j]+eps) * c_j  for i < nrows else 0.
// c_j is exactly 0 for j >= ncols, so vec4 over ceil(ncols/4) is exact.
// One warp per row, c staged in shared memory.
// -------------------------------------------------------------------------
__global__ void row_kernel(const float* __restrict__ s,
                           const int* __restrict__ nrows,
                           const int* __restrict__ ncols) {
    int b = blockIdx.y;
    __shared__ float4 cs[MM / 4];
    for (int t = threadIdx.x; t < MM / 4; t += blockDim.x)
        cs[t] = reinterpret_cast<const float4*>(g_c + (size_t)b * MM)[t];
    __syncthreads();

    int warp = threadIdx.x >> 5;
    int lane = threadIdx.x & 31;
    int nr = nrows[b];
    int nc = ncols[b];
    int nc4 = (nc + 3) >> 2;

#pragma unroll
    for (int rr = 0; rr < 8; rr++) {
        int i = blockIdx.x * 64 + warp * 8 + rr;
        if (i >= nr) {
            if (lane == 0) g_r[b * NN + i] = 0.0f;
            continue;
        }
        const float4* sp = reinterpret_cast<const float4*>(
            s + (size_t)b * NN * MM + (size_t)i * MM);
        float acc = 0.0f;
        for (int t = lane; t < nc4; t += 32) {
            float4 v = sp[t];
            float4 c = cs[t];
            acc += (v.x + EPSF) * c.x + (v.y + EPSF) * c.y +
                   (v.z + EPSF) * c.z + (v.w + EPSF) * c.w;
        }
#pragma unroll
        for (int o = 16; o; o >>= 1)
            acc += __shfl_down_sync(0xffffffffu, acc, o);
        if (lane == 0) g_r[b * NN + i] = 1.0f / acc;
    }
}

// -------------------------------------------------------------------------
// Column step (iters 2,4,6,8): c_j = 1 / sum_{i<nrows} (s[i,j]+eps)*r_i
// for j < ncols else 0. r staged in shared memory; loop only valid rows.
// -------------------------------------------------------------------------
__global__ void col_kernel(const float* __restrict__ s,
                           const int* __restrict__ nrows,
                           const int* __restrict__ ncols) {
    int b = blockIdx.y;
    __shared__ float rs[NN];
    int nr = nrows[b];
    for (int i = threadIdx.x; i < nr; i += blockDim.x)
        rs[i] = g_r[b * NN + i];
    __syncthreads();

    int j = blockIdx.x * blockDim.x + threadIdx.x;
    int nc = ncols[b];
    if (j >= nc) { g_c[b * MM + j] = 0.0f; return; }

    const float* sp = s + (size_t)b * NN * MM + j;
    float acc = 0.0f;
#pragma unroll 8
    for (int i = 0; i < nr; i++)
        acc += (sp[(size_t)i * MM] + EPSF) * rs[i];
    g_c[b * MM + j] = 1.0f / acc;
}

// -------------------------------------------------------------------------
// Final: out[i,j] = mask ? (s[i,j]+eps) * r_i * c_j : 0.
// One CTA per row, float4 stores. Skip s reads outside the mask.
// -------------------------------------------------------------------------
__global__ void final_kernel(const float* __restrict__ s,
                             const int* __restrict__ nrows,
                             const int* __restrict__ ncols,
                             float* __restrict__ out) {
    int b = blockIdx.y;
    int i = blockIdx.x;
    int t = threadIdx.x;  // 256 threads * float4 = 1024 cols
    size_t off = (size_t)b * NN * MM + (size_t)i * MM;
    float4* o4 = reinterpret_cast<float4*>(out + off);
    int nr = nrows[b];
    int nc = ncols[b];

    if (i >= nr || 4 * t >= nc) {
        o4[t] = make_float4(0.0f, 0.0f, 0.0f, 0.0f);
        return;
    }
    float r = g_r[b * NN + i];
    float4 c = reinterpret_cast<const float4*>(g_c + (size_t)b * MM)[t];
    float4 v = reinterpret_cast<const float4*>(s + off)[t];
    float4 o;
    o.x = (v.x + EPSF) * r * c.x;   // c is exactly 0 beyond ncols -> exact 0
    o.y = (v.y + EPSF) * r * c.y;
    o.z = (v.z + EPSF) * r * c.z;
    o.w = (v.w + EPSF) * r * c.w;
    o4[t] = o;
}

// -------------------------------------------------------------------------
extern "C" void kernel_launch(void* const* d_in, const int* in_sizes, int n_in,
                              void* d_out, int out_size) {
    const float* s    = (const float*)d_in[0];
    const int* nrows  = (const int*)d_in[1];
    const int* ncols  = (const int*)d_in[2];
    float* out        = (float*)d_out;
    int B = in_sizes[1];  // nrows element count
    if (B > MAXB) B = MAXB;

    dim3 gcol(MM / 128, B), bcol(128);
    dim3 grow(NN / 64, B),  brow(256);

    // iter 0: column normalization (full-column sums)
    colsum0_kernel<<<gcol, bcol>>>(s, ncols);

    // iters 1..8: row, col, row, col, row, col, row, col
    for (int k = 0; k < 4; k++) {
        row_kernel<<<grow, brow>>>(s, nrows, ncols);
        col_kernel<<<gcol, bcol>>>(s, nrows, ncols);
    }
    // iter 9: final row normalization
    row_kernel<<<grow, brow>>>(s, nrows, ncols);

    // materialize output
    final_kernel<<<dim3(NN, B), 256>>>(s, nrows, ncols, out);
}

// round 2
// speedup vs baseline: 1.2930x; 1.2930x over previous
#include <cuda_runtime.h>
#include <cuda_bf16.h>

#define B_ 64
#define N_ 1024
#define M_ 1024
#define EPSF 1e-4f
#define NTHREADS 1024
#define MAXGRID 128

// Cross-phase scale factors (L2-coherent via __stcg/__ldcg).
__device__ float g_r[B_ * N_];
__device__ float g_c[B_ * M_];

// Software grid barrier state. g_arrive always returns to 0 per barrier;
// g_release monotonically increases (wraps fine) -> graph-replay safe.
__device__ unsigned int g_arrive;
__device__ volatile unsigned int g_release;

__device__ __forceinline__ void grid_sync(unsigned nb) {
    __syncthreads();
    if (threadIdx.x == 0) {
        __threadfence();                    // drain this block's writes to L2
        unsigned gen = g_release;           // read gen BEFORE arriving
        __threadfence();
        if (atomicAdd(&g_arrive, 1) == nb - 1) {
            g_arrive = 0;                   // safe: all blocks have arrived
            __threadfence();
            g_release = gen + 1;            // release
        } else {
            while (g_release == gen) __nanosleep(64);
        }
    }
    __syncthreads();
}

// ---------------------------------------------------------------------------
// Column phase. FIRST=1: c_j = 1/(sum_{all i} s[i,j] + N*eps) for j<nc else 0.
// FIRST=0: c_j = 1/sum_{i<nr} (s[i,j]+eps)*r_i for j<nc else 0.
// Item = (batch, 32-quad group = 128 cols). Thread (sub,ql): 1 quad, rows
// strided by 32. 32 partials combined in smem.
// ---------------------------------------------------------------------------
template <int FIRST>
__device__ void col_phase(const float* __restrict__ s,
                          const int* __restrict__ nrows,
                          const int* __restrict__ ncols,
                          float4* smem, unsigned nb) {
    const int sub = threadIdx.x >> 5;   // 0..31 : row-stripe
    const int ql  = threadIdx.x & 31;   // 0..31 : quad within group
    for (int item = blockIdx.x; item < B_ * 8; item += nb) {
        int b  = item >> 3;
        int qg = item & 7;
        int qc = qg * 32 + ql;          // quad 0..255 -> cols 4*qc..4*qc+3
        int lim = FIRST ? N_ : __ldg(nrows + b);
        const float4* sp = reinterpret_cast<const float4*>(
                               s + (size_t)b * N_ * M_) + qc;
        const float* rp = g_r + b * N_;
        float4 acc = make_float4(0.f, 0.f, 0.f, 0.f);
#pragma unroll 4
        for (int i = sub; i < lim; i += 32) {
            float4 v = __ldg(sp + (size_t)i * (M_ / 4));
            if (FIRST) {
                acc.x += v.x; acc.y += v.y; acc.z += v.z; acc.w += v.w;
            } else {
                float w = __ldcg(rp + i);
                acc.x += (v.x + EPSF) * w;
                acc.y += (v.y + EPSF) * w;
                acc.z += (v.z + EPSF) * w;
                acc.w += (v.w + EPSF) * w;
            }
        }
        smem[sub * 32 + ql] = acc;
        __syncthreads();
        if (threadIdx.x < 32) {
            float4 t = smem[threadIdx.x];
#pragma unroll
            for (int k = 1; k < 32; k++) {
                float4 u = smem[k * 32 + threadIdx.x];
                t.x += u.x; t.y += u.y; t.z += u.z; t.w += u.w;
            }
            int nc = __ldg(ncols + b);
            int j0 = (qg * 32 + threadIdx.x) * 4;
            float extra = FIRST ? (float)N_ * EPSF : 0.f;
            float4 o;
            o.x = (j0 + 0 < nc) ? 1.f / (t.x + extra) : 0.f;
            o.y = (j0 + 1 < nc) ? 1.f / (t.y + extra) : 0.f;
            o.z = (j0 + 2 < nc) ? 1.f / (t.z + extra) : 0.f;
            o.w = (j0 + 3 < nc) ? 1.f / (t.w + extra) : 0.f;
            __stcg(reinterpret_cast<float4*>(g_c + b * M_) +
                       (qg * 32 + threadIdx.x),
                   o);
        }
        __syncthreads();
    }
}

// ---------------------------------------------------------------------------
// Row phase: r_i = 1/sum_{j<nc} (s[i,j]+eps)*c_j for i<nr else 0.
// Item = (batch, 32-row group); one warp per row, float4 lane-strided loads.
// c_j == 0 exactly for j>=nc, so the vec4 tail is exact.
// ---------------------------------------------------------------------------
__device__ void row_phase(const float* __restrict__ s,
                          const int* __restrict__ nrows,
                          const int* __restrict__ ncols, unsigned nb) {
    const int warp = threadIdx.x >> 5;
    const int lane = threadIdx.x & 31;
    for (int item = blockIdx.x; item < B_ * 32; item += nb) {
        int b = item >> 5;
        int i = ((item & 31) << 5) + warp;
        int nr = __ldg(nrows + b);
        if (i < nr) {
            int nc4 = (__ldg(ncols + b) + 3) >> 2;
            const float4* sp = reinterpret_cast<const float4*>(
                s + (size_t)b * N_ * M_ + (size_t)i * M_);
            const float4* cp = reinterpret_cast<const float4*>(g_c + b * M_);
            float acc = 0.f;
#pragma unroll 2
            for (int t = lane; t < nc4; t += 32) {
                float4 v = __ldg(sp + t);
                float4 c = __ldcg(cp + t);
                acc += (v.x + EPSF) * c.x + (v.y + EPSF) * c.y +
                       (v.z + EPSF) * c.z + (v.w + EPSF) * c.w;
            }
#pragma unroll
            for (int o = 16; o; o >>= 1)
                acc += __shfl_down_sync(0xffffffffu, acc, o);
            if (lane == 0) __stcg(&g_r[b * N_ + i], 1.f / acc);
        } else {
            if (lane == 0) __stcg(&g_r[b * N_ + i], 0.f);
        }
    }
}

// ---------------------------------------------------------------------------
// Output: out[i,j] = mask ? (s+eps)*r_i*c_j : 0. Linear float4 sweep.
// ---------------------------------------------------------------------------
__device__ void out_phase(const float* __restrict__ s,
                          const int* __restrict__ nrows,
                          const int* __restrict__ ncols,
                          float* __restrict__ out, unsigned nb) {
    const int total = B_ * N_ * (M_ / 4);  // 16M float4
    for (int t = blockIdx.x * NTHREADS + threadIdx.x; t < total;
         t += nb * NTHREADS) {
        int b   = t >> 18;
        int rem = t & 262143;
        int i   = rem >> 8;
        int q   = rem & 255;
        float4 o = make_float4(0.f, 0.f, 0.f, 0.f);
        if (i < __ldg(nrows + b) && 4 * q < __ldg(ncols + b)) {
            float  r = __ldcg(&g_r[b * N_ + i]);
            float4 c = __ldcg(reinterpret_cast<const float4*>(g_c + b * M_) + q);
            float4 v = __ldg(reinterpret_cast<const float4*>(s) + t);
            o.x = (v.x + EPSF) * r * c.x;  // c exactly 0 beyond nc
            o.y = (v.y + EPSF) * r * c.y;
            o.z = (v.z + EPSF) * r * c.z;
            o.w = (v.w + EPSF) * r * c.w;
        }
        reinterpret_cast<float4*>(out)[t] = o;
    }
}

// ---------------------------------------------------------------------------
__global__ void __launch_bounds__(NTHREADS, 1)
sinkhorn_kernel(const float* __restrict__ s, const int* __restrict__ nrows,
                const int* __restrict__ ncols, float* __restrict__ out) {
    __shared__ float4 smem[NTHREADS];  // 16 KB
    const unsigned nb = gridDim.x;

    col_phase<1>(s, nrows, ncols, smem, nb);      // iter 0
    grid_sync(nb);
#pragma unroll 1
    for (int k = 0; k < 4; k++) {                 // iters 1..8
        row_phase(s, nrows, ncols, nb);
        grid_sync(nb);
        col_phase<0>(s, nrows, ncols, smem, nb);
        grid_sync(nb);
    }
    row_phase(s, nrows, ncols, nb);               // iter 9
    grid_sync(nb);
    out_phase(s, nrows, ncols, out, nb);
}

extern "C" void kernel_launch(void* const* d_in, const int* in_sizes, int n_in,
                              void* d_out, int out_size) {
    const float* s   = (const float*)d_in[0];
    const int* nrows = (const int*)d_in[1];
    const int* ncols = (const int*)d_in[2];
    float* out       = (float*)d_out;

    // Co-residency guarantee for the software grid barrier.
    int dev = 0;
    cudaGetDevice(&dev);
    int sms = 0;
    cudaDeviceGetAttribute(&sms, cudaDevAttrMultiProcessorCount, dev);
    int bpm = 0;
    cudaOccupancyMaxActiveBlocksPerMultiprocessor(&bpm, sinkhorn_kernel,
                                                  NTHREADS, 0);
    int grid = sms * bpm;
    if (grid > MAXGRID) grid = MAXGRID;
    if (grid < 1) grid = 1;

    sinkhorn_kernel<<<grid, NTHREADS>>>(s, nrows, ncols, out);
}

// round 3
// speedup vs baseline: 1.5934x; 1.2323x over previous
#include <cuda_runtime.h>
#include <cuda_bf16.h>

#define B_ 64
#define N_ 1024
#define M_ 1024
#define Q_ 256          // float4 per row
#define EPSF 1e-4f
#define NT 256          // threads per block (8 warps)
#define RG 16           // rows per warp-item
#define NG 64           // row-groups per batch (N_/RG)
#define U_ 8            // float4 per lane per row (Q_/32)

// Scratch (deterministic fixed-order reductions; no data atomics).
__device__ float g_part[B_ * NG * M_];   // 16 MB per-item column partials
__device__ float g_c[B_ * M_];           // current column factors
__device__ unsigned int g_arrive;
__device__ volatile unsigned int g_release;

__device__ __forceinline__ void grid_sync(unsigned nb) {
    __syncthreads();
    if (threadIdx.x == 0) {
        __threadfence();
        unsigned gen = g_release;
        __threadfence();
        if (atomicAdd(&g_arrive, 1) == nb - 1) {
            g_arrive = 0;
            __threadfence();
            g_release = gen + 1;
        } else {
            while (g_release == gen) __nanosleep(64);
        }
    }
    __syncthreads();
}

__device__ __forceinline__ float warp_sum(float v) {
#pragma unroll
    for (int o = 16; o; o >>= 1) v += __shfl_xor_sync(0xffffffffu, v, o);
    return v;
}

// ---------------------------------------------------------------------------
// P0: iter 0 column partial sums. Per warp-item (b, 16 rows): sum raw s over
// the 16 rows into register col-accumulators, write 4KB partial. ALL rows.
// ---------------------------------------------------------------------------
__device__ void phase0(const float* __restrict__ s,
                       const int* __restrict__ ncols,
                       int gw, int tw, int lane) {
    for (int item = gw; item < B_ * NG; item += tw) {
        int b = item >> 6, rg = item & 63;
        int nq = (__ldg(ncols + b) + 3) >> 2;
        const float4* sp = reinterpret_cast<const float4*>(s) +
                           ((size_t)b * N_ + rg * RG) * Q_;
        float4 acc[U_];
#pragma unroll
        for (int u = 0; u < U_; u++) acc[u] = make_float4(0.f, 0.f, 0.f, 0.f);
        for (int r = 0; r < RG; r++) {
#pragma unroll
            for (int u = 0; u < U_; u++) {
                int q = lane + 32 * u;
                if (q < nq) {
                    float4 v = __ldg(sp + r * Q_ + q);
                    acc[u].x += v.x; acc[u].y += v.y;
                    acc[u].z += v.z; acc[u].w += v.w;
                }
            }
        }
        float4* pp = reinterpret_cast<float4*>(g_part) + (size_t)item * Q_;
#pragma unroll
        for (int u = 0; u < U_; u++) __stcg(pp + lane + 32 * u, acc[u]);
    }
}

// ---------------------------------------------------------------------------
// Finalize: c_j = 1/sum(partials) (masked). FIRST adds N*eps to the sum.
// Fixed-order serial sum over groups -> deterministic.
// ---------------------------------------------------------------------------
template <int FIRST>
__device__ void finalize(const int* __restrict__ nrows,
                         const int* __restrict__ ncols,
                         int gtid, int gthreads) {
    const float4* pp = reinterpret_cast<const float4*>(g_part);
    float4* cp = reinterpret_cast<float4*>(g_c);
    for (int t = gtid; t < B_ * Q_; t += gthreads) {
        int b = t >> 8, q = t & 255;
        int nc = __ldg(ncols + b);
        int G = FIRST ? NG : min(NG, (__ldg(nrows + b) + RG - 1) / RG);
        float4 sum = make_float4(0.f, 0.f, 0.f, 0.f);
        for (int g = 0; g < G; g++) {
            float4 v = __ldcg(pp + ((size_t)b * NG + g) * Q_ + q);
            sum.x += v.x; sum.y += v.y; sum.z += v.z; sum.w += v.w;
        }
        if (FIRST) {
            const float e = (float)N_ * EPSF;
            sum.x += e; sum.y += e; sum.z += e; sum.w += e;
        }
        int j0 = 4 * q;
        float4 c;
        c.x = (j0 + 0 < nc && sum.x > 0.f) ? 1.f / sum.x : 0.f;
        c.y = (j0 + 1 < nc && sum.y > 0.f) ? 1.f / sum.y : 0.f;
        c.z = (j0 + 2 < nc && sum.z > 0.f) ? 1.f / sum.z : 0.f;
        c.w = (j0 + 3 < nc && sum.w > 0.f) ? 1.f / sum.w : 0.f;
        __stcg(cp + t, c);
    }
}

// ---------------------------------------------------------------------------
// Fused row+col pass (iters 2k-1 and 2k). Per warp-item (b, 16 valid rows):
// stage c in regs; per row compute r_i = 1/<s0,c>, then acc += s0 * r_i.
// Second read of the row hits L1. Write 4KB column partial per item.
// ---------------------------------------------------------------------------
__device__ void fused_pass(const float* __restrict__ s,
                           const int* __restrict__ nrows,
                           const int* __restrict__ ncols,
                           int gw, int tw, int lane) {
    for (int item = gw; item < B_ * NG; item += tw) {
        int b = item >> 6, rg = item & 63;
        int nr = __ldg(nrows + b);
        if (rg * RG >= nr) continue;  // partial not read by finalize
        int nq = (__ldg(ncols + b) + 3) >> 2;
        const float4* sp = reinterpret_cast<const float4*>(s) +
                           ((size_t)b * N_ + rg * RG) * Q_;
        const float4* cp = reinterpret_cast<const float4*>(g_c) + b * Q_;
        float4 c[U_], acc[U_];
#pragma unroll
        for (int u = 0; u < U_; u++) {
            c[u] = __ldcg(cp + lane + 32 * u);
            acc[u] = make_float4(0.f, 0.f, 0.f, 0.f);
        }
        int rows = min(RG, nr - rg * RG);
        for (int r = 0; r < rows; r++) {
            float rs = 0.f;
#pragma unroll
            for (int u = 0; u < U_; u++) {
                int q = lane + 32 * u;
                if (q < nq) {
                    float4 v = __ldg(sp + r * Q_ + q);
                    rs += (v.x + EPSF) * c[u].x + (v.y + EPSF) * c[u].y +
                          (v.z + EPSF) * c[u].z + (v.w + EPSF) * c[u].w;
                }
            }
            rs = warp_sum(rs);
            float rinv = (rs > 0.f) ? 1.f / rs : 0.f;
#pragma unroll
            for (int u = 0; u < U_; u++) {
                int q = lane + 32 * u;
                if (q < nq) {
                    float4 v = __ldg(sp + r * Q_ + q);  // L1 hit
                    acc[u].x += (v.x + EPSF) * rinv;
                    acc[u].y += (v.y + EPSF) * rinv;
                    acc[u].z += (v.z + EPSF) * rinv;
                    acc[u].w += (v.w + EPSF) * rinv;
                }
            }
        }
        float4* pp = reinterpret_cast<float4*>(g_part) + (size_t)item * Q_;
#pragma unroll
        for (int u = 0; u < U_; u++) __stcg(pp + lane + 32 * u, acc[u]);
    }
}

// ---------------------------------------------------------------------------
// Final pass: iter 9 (row) fused with output. out = mask ? s0*r_i*c_j : 0.
// ---------------------------------------------------------------------------
__device__ void final_pass(const float* __restrict__ s,
                           const int* __restrict__ nrows,
                           const int* __restrict__ ncols,
                           float* __restrict__ out,
                           int gw, int tw, int lane) {
    const float4 z = make_float4(0.f, 0.f, 0.f, 0.f);
    for (int item = gw; item < B_ * NG; item += tw) {
        int b = item >> 6, rg = item & 63;
        int nr = __ldg(nrows + b);
        float4* op = reinterpret_cast<float4*>(out) +
                     ((size_t)b * N_ + rg * RG) * Q_;
        if (rg * RG >= nr) {  // fully invalid rows -> zeros
            for (int r = 0; r < RG; r++)
#pragma unroll
                for (int u = 0; u < U_; u++)
                    __stcg(op + r * Q_ + lane + 32 * u, z);
            continue;
        }
        int nq = (__ldg(ncols + b) + 3) >> 2;
        const float4* sp = reinterpret_cast<const float4*>(s) +
                           ((size_t)b * N_ + rg * RG) * Q_;
        const float4* cp = reinterpret_cast<const float4*>(g_c) + b * Q_;
        float4 c[U_];
#pragma unroll
        for (int u = 0; u < U_; u++) c[u] = __ldcg(cp + lane + 32 * u);
        for (int r = 0; r < RG; r++) {
            int i = rg * RG + r;
            if (i < nr) {
                float rs = 0.f;
#pragma unroll
                for (int u = 0; u < U_; u++) {
                    int q = lane + 32 * u;
                    if (q < nq) {
                        float4 v = __ldg(sp + r * Q_ + q);
                        rs += (v.x + EPSF) * c[u].x + (v.y + EPSF) * c[u].y +
                              (v.z + EPSF) * c[u].z + (v.w + EPSF) * c[u].w;
                    }
                }
                rs = warp_sum(rs);
                float rinv = (rs > 0.f) ? 1.f / rs : 0.f;
#pragma unroll
                for (int u = 0; u < U_; u++) {
                    int q = lane + 32 * u;
                    float4 o = z;
                    if (q < nq) {
                        float4 v = __ldg(sp + r * Q_ + q);  // L1 hit
                        o.x = (v.x + EPSF) * rinv * c[u].x;  // c==0 past nc
                        o.y = (v.y + EPSF) * rinv * c[u].y;
                        o.z = (v.z + EPSF) * rinv * c[u].z;
                        o.w = (v.w + EPSF) * rinv * c[u].w;
                    }
                    __stcg(op + r * Q_ + q, o);
                }
            } else {
#pragma unroll
                for (int u = 0; u < U_; u++)
                    __stcg(op + r * Q_ + lane + 32 * u, z);
            }
        }
    }
}

// ---------------------------------------------------------------------------
__global__ void __launch_bounds__(NT)
sinkhorn_kernel(const float* __restrict__ s, const int* __restrict__ nrows,
                const int* __restrict__ ncols, float* __restrict__ out) {
    const unsigned nb = gridDim.x;
    const int lane = threadIdx.x & 31;
    const int gw = blockIdx.x * (NT / 32) + (threadIdx.x >> 5);
    const int tw = nb * (NT / 32);
    const int gtid = blockIdx.x * NT + threadIdx.x;
    const int gthreads = nb * NT;

    phase0(s, ncols, gw, tw, lane);          // iter 0 (col partials)
    grid_sync(nb);
    finalize<1>(nrows, ncols, gtid, gthreads);
    grid_sync(nb);
#pragma unroll 1
    for (int k = 0; k < 4; k++) {            // iters 1..8 (4 fused passes)
        fused_pass(s, nrows, ncols, gw, tw, lane);
        grid_sync(nb);
        finalize<0>(nrows, ncols, gtid, gthreads);
        grid_sync(nb);
    }
    final_pass(s, nrows, ncols, out, gw, tw, lane);  // iter 9 + output
}

extern "C" void kernel_launch(void* const* d_in, const int* in_sizes, int n_in,
                              void* d_out, int out_size) {
    const float* s   = (const float*)d_in[0];
    const int* nrows = (const int*)d_in[1];
    const int* ncols = (const int*)d_in[2];
    float* out       = (float*)d_out;

    int dev = 0;
    cudaGetDevice(&dev);
    int sms = 0;
    cudaDeviceGetAttribute(&sms, cudaDevAttrMultiProcessorCount, dev);
    int bpm = 0;
    cudaOccupancyMaxActiveBlocksPerMultiprocessor(&bpm, sinkhorn_kernel, NT, 0);
    int grid = sms * bpm;
    if (grid < 1) grid = 1;

    sinkhorn_kernel<<<grid, NT>>>(s, nrows, ncols, out);
}

// round 4
// speedup vs baseline: 2.0534x; 1.2887x over previous
#include <cuda_runtime.h>
#include <cuda_fp16.h>

#define B_ 64
#define N_ 1024
#define M_ 1024
#define Q_ 256          // float4 per row
#define EPSF 1e-4f
#define NT 128
#define RG 8            // rows per item
#define NG 128          // N_/RG
#define U_ 8            // float4-quads per lane (Q_/32)

__device__ float  g_part[(size_t)B_ * NG * M_];   // 32 MB column partials
__device__ __half g_h[(size_t)B_ * N_ * M_];      // 128 MB fp16 copy of s+eps
__device__ float  g_c[B_ * M_];                   // current column factors
__device__ unsigned g_ctr[8];                     // work-steal counters
__device__ unsigned g_arrive;
__device__ volatile unsigned g_release;

__device__ __forceinline__ void grid_sync(unsigned nb) {
    __syncthreads();
    if (threadIdx.x == 0) {
        __threadfence();
        unsigned gen = g_release;
        __threadfence();
        if (atomicAdd(&g_arrive, 1) == nb - 1) {
            g_arrive = 0;
            __threadfence();
            g_release = gen + 1;
        } else {
            while (g_release == gen) __nanosleep(64);
        }
    }
    __syncthreads();
}

__device__ __forceinline__ float warp_sum(float v) {
#pragma unroll
    for (int o = 16; o; o >>= 1) v += __shfl_xor_sync(0xffffffffu, v, o);
    return v;
}

__device__ __forceinline__ int steal(unsigned* c, int lane) {
    unsigned v = 0;
    if (lane == 0) v = atomicAdd(c, 1u);
    return (int)__shfl_sync(0xffffffffu, v, 0);
}

__device__ __forceinline__ void pf_l1(const void* p) {
    asm volatile("prefetch.global.L1 [%0];" :: "l"(p));
}

// ---------------------------------------------------------------------------
// P0: iter-0 column partials over ALL rows + write fp16 copy (s+eps) for
// valid rows. Work-stolen items of 8 rows.
// ---------------------------------------------------------------------------
__device__ void phase0(const float4* __restrict__ s4,
                       const int* __restrict__ nrows,
                       const int* __restrict__ ncols, int lane) {
    for (;;) {
        int item = steal(&g_ctr[0], lane);
        if (item >= B_ * NG) break;
        int b = item >> 7, rg = item & (NG - 1);
        int nc = __ldg(ncols + b), nr = __ldg(nrows + b);
        int nq = (nc + 3) >> 2;
        const float4* sp = s4 + (size_t)(b * N_ + rg * RG) * Q_;
        __half* hp = g_h + (size_t)(b * N_ + rg * RG) * M_;
        float4 acc[U_];
#pragma unroll
        for (int u = 0; u < U_; u++) acc[u] = make_float4(0.f, 0.f, 0.f, 0.f);
        bool pfl = (lane * 32 < nc);
        if (pfl) {
            pf_l1((const char*)sp + lane * 128);
            pf_l1((const char*)(sp + Q_) + lane * 128);
        }
        for (int r = 0; r < RG; r++) {
            if (pfl && r + 2 < RG) pf_l1((const char*)(sp + (r + 2) * Q_) + lane * 128);
            bool wr = (rg * RG + r) < nr;
#pragma unroll
            for (int u = 0; u < U_; u++) {
                int q = lane + 32 * u;
                if (q < nq) {
                    float4 v = __ldg(sp + r * Q_ + q);
                    acc[u].x += v.x; acc[u].y += v.y;
                    acc[u].z += v.z; acc[u].w += v.w;
                    if (wr) {
                        __half2 h0 = __floats2half2_rn(v.x + EPSF, v.y + EPSF);
                        __half2 h1 = __floats2half2_rn(v.z + EPSF, v.w + EPSF);
                        uint2 pk;
                        pk.x = *reinterpret_cast<unsigned*>(&h0);
                        pk.y = *reinterpret_cast<unsigned*>(&h1);
                        reinterpret_cast<uint2*>(hp + (size_t)r * M_)[q] = pk;
                    }
                }
            }
        }
        float4* pp = reinterpret_cast<float4*>(g_part) + (size_t)item * Q_;
#pragma unroll
        for (int u = 0; u < U_; u++) __stcg(pp + lane + 32 * u, acc[u]);
    }
}

// ---------------------------------------------------------------------------
// Finalize: c_j = 1/sum(group partials), masked. One scalar per thread.
// Fixed summation order -> deterministic.
// ---------------------------------------------------------------------------
template <int FIRST>
__device__ void finalize(const int* __restrict__ nrows,
                         const int* __restrict__ ncols,
                         int gtid, int gthreads) {
    for (int t = gtid; t < B_ * M_; t += gthreads) {
        int b = t >> 10, j = t & (M_ - 1);
        int nc = __ldg(ncols + b);
        int G = FIRST ? NG : min(NG, (__ldg(nrows + b) + RG - 1) / RG);
        const float* pp = g_part + (size_t)b * NG * M_ + j;
        float a0 = 0.f, a1 = 0.f, a2 = 0.f, a3 = 0.f;
        int g = 0;
        for (; g + 4 <= G; g += 4) {
            a0 += __ldcg(pp + (size_t)(g + 0) * M_);
            a1 += __ldcg(pp + (size_t)(g + 1) * M_);
            a2 += __ldcg(pp + (size_t)(g + 2) * M_);
            a3 += __ldcg(pp + (size_t)(g + 3) * M_);
        }
        for (; g < G; g++) a0 += __ldcg(pp + (size_t)g * M_);
        float sum = ((a0 + a1) + (a2 + a3)) + (FIRST ? (float)N_ * EPSF : 0.f);
        float cv = (j < nc && sum > 0.f) ? 1.f / sum : 0.f;
        __stcg(&g_c[t], cv);
    }
}

// ---------------------------------------------------------------------------
// Fused row+col pass over fp16 copy. Valid items only (work-stolen), mapped
// via prefix array + binary search. Row held in regs (no second load).
// ---------------------------------------------------------------------------
__device__ void fused(const int* __restrict__ nrows,
                      const int* __restrict__ ncols,
                      int lane, unsigned* ctr, const int* vpre) {
    int count = vpre[B_];
    for (;;) {
        int idx = steal(ctr, lane);
        if (idx >= count) break;
        int lo = 0, hi = B_;
        while (hi - lo > 1) {
            int mid = (lo + hi) >> 1;
            if (vpre[mid] <= idx) lo = mid; else hi = mid;
        }
        int b = lo, rg = idx - vpre[b];
        int nr = __ldg(nrows + b), nc = __ldg(ncols + b);
        int nq = (nc + 3) >> 2;
        int i0 = rg * RG;
        int rows = min(RG, nr - i0);
        const uint2* hp = reinterpret_cast<const uint2*>(
            g_h + (size_t)(b * N_ + i0) * M_);
        const float4* cp = reinterpret_cast<const float4*>(g_c) + b * Q_;
        float4 c[U_], acc[U_];
#pragma unroll
        for (int u = 0; u < U_; u++) {
            c[u] = __ldcg(cp + lane + 32 * u);
            acc[u] = make_float4(0.f, 0.f, 0.f, 0.f);
        }
        bool pfl = (lane < 16) && (lane * 64 < nc);
        if (pfl) {
            pf_l1((const char*)hp + lane * 128);
            if (rows > 1) pf_l1((const char*)(hp + Q_) + lane * 128);
        }
        for (int r = 0; r < rows; r++) {
            if (pfl && r + 2 < rows) pf_l1((const char*)(hp + (r + 2) * Q_) + lane * 128);
            uint2 h[U_];
            float rs = 0.f;
#pragma unroll
            for (int u = 0; u < U_; u++) {
                int q = lane + 32 * u;
                if (q < nq) {
                    h[u] = __ldg(hp + r * Q_ + q);
                    float2 a = __half22float2(*reinterpret_cast<__half2*>(&h[u].x));
                    float2 d = __half22float2(*reinterpret_cast<__half2*>(&h[u].y));
                    rs += a.x * c[u].x + a.y * c[u].y + d.x * c[u].z + d.y * c[u].w;
                }
            }
            rs = warp_sum(rs);
            float rinv = (rs > 0.f) ? 1.f / rs : 0.f;
#pragma unroll
            for (int u = 0; u < U_; u++) {
                int q = lane + 32 * u;
                if (q < nq) {
                    float2 a = __half22float2(*reinterpret_cast<__half2*>(&h[u].x));
                    float2 d = __half22float2(*reinterpret_cast<__half2*>(&h[u].y));
                    acc[u].x += a.x * rinv; acc[u].y += a.y * rinv;
                    acc[u].z += d.x * rinv; acc[u].w += d.y * rinv;
                }
            }
        }
        float4* pp = reinterpret_cast<float4*>(g_part) + (size_t)(b * NG + rg) * Q_;
#pragma unroll
        for (int u = 0; u < U_; u++) __stcg(pp + lane + 32 * u, acc[u]);
    }
}

// ---------------------------------------------------------------------------
// Final: iter-9 row norm (fp32) fused with masked output write.
// ---------------------------------------------------------------------------
__device__ void final_pass(const float4* __restrict__ s4,
                           const int* __restrict__ nrows,
                           const int* __restrict__ ncols,
                           float4* __restrict__ o4, int gw, int tw, int lane) {
    const float4 z = make_float4(0.f, 0.f, 0.f, 0.f);
    for (int item = gw; item < B_ * NG; item += tw) {
        int b = item >> 7, rg = item & (NG - 1);
        int nr = __ldg(nrows + b);
        int i0 = rg * RG;
        float4* op = o4 + (size_t)(b * N_ + i0) * Q_;
        if (i0 >= nr) {
            for (int r = 0; r < RG; r++)
#pragma unroll
                for (int u = 0; u < U_; u++)
                    __stcg(op + r * Q_ + lane + 32 * u, z);
            continue;
        }
        int nc = __ldg(ncols + b);
        int nq = (nc + 3) >> 2;
        int rows = min(RG, nr - i0);
        const float4* sp = s4 + (size_t)(b * N_ + i0) * Q_;
        const float4* cp = reinterpret_cast<const float4*>(g_c) + b * Q_;
        float4 c[U_];
#pragma unroll
        for (int u = 0; u < U_; u++) c[u] = __ldcg(cp + lane + 32 * u);
        bool pfl = (lane * 32 < nc);
        if (pfl) {
            pf_l1((const char*)sp + lane * 128);
            if (rows > 1) pf_l1((const char*)(sp + Q_) + lane * 128);
        }
        for (int r = 0; r < RG; r++) {
            int i = i0 + r;
            if (i < nr) {
                if (pfl && r + 2 < rows) pf_l1((const char*)(sp + (r + 2) * Q_) + lane * 128);
                float rs = 0.f;
#pragma unroll
                for (int u = 0; u < U_; u++) {
                    int q = lane + 32 * u;
                    if (q < nq) {
                        float4 v = __ldg(sp + r * Q_ + q);
                        rs += (v.x + EPSF) * c[u].x + (v.y + EPSF) * c[u].y +
                              (v.z + EPSF) * c[u].z + (v.w + EPSF) * c[u].w;
                    }
                }
                rs = warp_sum(rs);
                float rinv = (rs > 0.f) ? 1.f / rs : 0.f;
#pragma unroll
                for (int u = 0; u < U_; u++) {
                    int q = lane + 32 * u;
                    float4 o = z;
                    if (q < nq) {
                        float4 v = __ldg(sp + r * Q_ + q);  // L1 hit
                        o.x = (v.x + EPSF) * rinv * c[u].x;  // c==0 past nc
                        o.y = (v.y + EPSF) * rinv * c[u].y;
                        o.z = (v.z + EPSF) * rinv * c[u].z;
                        o.w = (v.w + EPSF) * rinv * c[u].w;
                    }
                    __stcg(op + r * Q_ + lane + 32 * u, o);
                }
            } else {
#pragma unroll
                for (int u = 0; u < U_; u++)
                    __stcg(op + r * Q_ + lane + 32 * u, z);
            }
        }
    }
}

// ---------------------------------------------------------------------------
__global__ void __launch_bounds__(NT)
sinkhorn_kernel(const float* __restrict__ s, const int* __restrict__ nrows,
                const int* __restrict__ ncols, float* __restrict__ out) {
    __shared__ int vpre[B_ + 1];
    if (threadIdx.x == 0) {
        int a = 0;
        for (int b = 0; b < B_; b++) {
            vpre[b] = a;
            a += (__ldg(nrows + b) + RG - 1) / RG;
        }
        vpre[B_] = a;
    }
    __syncthreads();

    const unsigned nb = gridDim.x;
    const int lane = threadIdx.x & 31;
    const int gw = blockIdx.x * (NT / 32) + (threadIdx.x >> 5);
    const int tw = nb * (NT / 32);
    const int gtid = blockIdx.x * NT + threadIdx.x;
    const int gthreads = nb * NT;
    const float4* s4 = reinterpret_cast<const float4*>(s);
    float4* o4 = reinterpret_cast<float4*>(out);

    phase0(s4, nrows, ncols, lane);          // iter 0 partials + fp16 copy
    grid_sync(nb);
    finalize<1>(nrows, ncols, gtid, gthreads);
    grid_sync(nb);
#pragma unroll 1
    for (int k = 0; k < 4; k++) {            // iters 1..8
        fused(nrows, ncols, lane, &g_ctr[1 + k], vpre);
        grid_sync(nb);
        finalize<0>(nrows, ncols, gtid, gthreads);
        grid_sync(nb);
    }
    // reset work-steal counters for the next graph replay (all uses done)
    if (blockIdx.x == 0 && threadIdx.x < 8) g_ctr[threadIdx.x] = 0;

    final_pass(s4, nrows, ncols, o4, gw, tw, lane);  // iter 9 + output
}

extern "C" void kernel_launch(void* const* d_in, const int* in_sizes, int n_in,
                              void* d_out, int out_size) {
    const float* s   = (const float*)d_in[0];
    const int* nrows = (const int*)d_in[1];
    const int* ncols = (const int*)d_in[2];
    float* out       = (float*)d_out;

    int dev = 0;
    cudaGetDevice(&dev);
    int sms = 0;
    cudaDeviceGetAttribute(&sms, cudaDevAttrMultiProcessorCount, dev);
    int bpm = 0;
    cudaOccupancyMaxActiveBlocksPerMultiprocessor(&bpm, sinkhorn_kernel, NT, 0);
    int grid = sms * bpm;
    if (grid < 1) grid = 1;

    sinkhorn_kernel<<<grid, NT>>>(s, nrows, ncols, out);
}